// round 5
// baseline (speedup 1.0000x reference)
#include <cuda_runtime.h>
#include <math.h>

#define BB 64
#define AA 8732
#define CC 81
#define GG 32
#define NEG_RATIO 3
#define IOU_THR 0.5f
#define NB1 35         // k1/k3 blocks per batch along anchors: ceil(8732/256)=35
#define RPB 64         // rows per k3 block (8 warps x 8 rows)

// ---------------- device scratch (no allocs allowed) ----------------
__device__ float4             g_tloc[BB * AA];        // encoded loc targets (valid only where lab>0)
__device__ int                g_tlab[BB * AA];        // class targets (0 = background)
__device__ unsigned long long g_bpp[BB * NB1 * GG];   // per-block best-prior partials
__device__ float              g_clsl[BB * AA];        // negative mining loss per anchor
__device__ int                g_numpos[BB];
__device__ float              g_locsum[BB];
__device__ float              g_clspos[BB];
__device__ float              g_clsneg[BB];
__device__ int                g_done;

__device__ __forceinline__ float smooth_l1(float d) {
    float ad = fabsf(d);
    return ad < 1.0f ? 0.5f * d * d : ad - 0.5f;
}

__device__ __forceinline__ void cp_async16(void* smem_dst, const void* gsrc) {
    unsigned s = (unsigned)__cvta_generic_to_shared(smem_dst);
    asm volatile("cp.async.cg.shared.global [%0], [%1], 16;\n" :: "r"(s), "l"(gsrc));
}
__device__ __forceinline__ void cp_async_commit() {
    asm volatile("cp.async.commit_group;\n");
}
template <int N>
__device__ __forceinline__ void cp_async_wait() {
    asm volatile("cp.async.wait_group %0;\n" :: "n"(N));
}

// ---------------- K1: matching + per-gt best-anchor partials + scratch reset ----------
__global__ void __launch_bounds__(256)
k1_match(const float4* __restrict__ anchors,
         const float4* __restrict__ gt_boxes,
         const int*    __restrict__ gt_labels) {
    int b = blockIdx.y;
    __shared__ float gx1[GG], gy1[GG], gx2[GG], gy2[GG], garea[GG];
    __shared__ float gcx[GG], gcy[GG], gw[GG], gh[GG];
    __shared__ int   glab[GG];
    __shared__ unsigned long long sbp[GG];
    int t = threadIdx.x;

    // fold former k0 into k1 (k1 fully precedes k3/k4 in stream order)
    if (blockIdx.x == 0 && t == 0) {
        g_numpos[b] = 0;
        g_locsum[b] = 0.0f;
        g_clspos[b] = 0.0f;
        if (b == 0) g_done = 0;
    }

    if (t < GG) {
        float4 g = gt_boxes[b * GG + t];
        float x1 = g.x - g.z * 0.5f, y1 = g.y - g.w * 0.5f;
        float x2 = g.x + g.z * 0.5f, y2 = g.y + g.w * 0.5f;
        gx1[t] = x1; gy1[t] = y1; gx2[t] = x2; gy2[t] = y2;
        garea[t] = (x2 - x1) * (y2 - y1);
        gcx[t] = g.x; gcy[t] = g.y; gw[t] = g.z; gh[t] = g.w;
        glab[t] = gt_labels[b * GG + t];
        sbp[t] = 0xFFFFFFFFull;  // value 0, anchor 0
    }
    __syncthreads();

    int a = blockIdx.x * 256 + t;
    bool valid = a < AA;

    float4 an = valid ? anchors[a] : make_float4(2.0f, 2.0f, 0.01f, 0.01f);
    float ax1 = an.x - an.z * 0.5f, ay1 = an.y - an.w * 0.5f;
    float ax2 = an.x + an.z * 0.5f, ay2 = an.y + an.w * 0.5f;
    float aarea = (ax2 - ax1) * (ay2 - ay1);

    int warpbase = blockIdx.x * 256 + (t & ~31);
    float best = -1.0f;
    int   bidx = 0;
#pragma unroll 4
    for (int g = 0; g < GG; g++) {
        float ltx = fmaxf(gx1[g], ax1), lty = fmaxf(gy1[g], ay1);
        float rbx = fminf(gx2[g], ax2), rby = fminf(gy2[g], ay2);
        float w = fmaxf(rbx - ltx, 0.0f), h = fmaxf(rby - lty, 0.0f);
        float inter = w * h;
        bool ov = valid && (inter > 0.0f);
        float iou = ov ? __fdividef(inter, garea[g] + aarea - inter) : 0.0f;
        if (valid && iou > best) { best = iou; bidx = g; }  // first-index wins

        if (__any_sync(0xffffffffu, ov)) {
            unsigned ib = ov ? __float_as_uint(iou) : 0u;
            unsigned mx = __reduce_max_sync(0xffffffffu, ib);
            unsigned ball = __ballot_sync(0xffffffffu, ib == mx);
            if ((t & 31) == 0) {
                unsigned win_a = (unsigned)warpbase + (unsigned)(__ffs(ball) - 1);
                unsigned long long key =
                    (((unsigned long long)mx) << 32) |
                    (unsigned long long)(0xFFFFFFFFu - win_a);
                atomicMax(&sbp[g], key);
            }
        }
    }

    if (valid) {
        size_t idx = (size_t)b * AA + a;
        if (best > IOU_THR) {
            float4 enc;
            enc.x = (gcx[bidx] - an.x) / an.z;
            enc.y = (gcy[bidx] - an.y) / an.w;
            enc.z = logf(gw[bidx]) - logf(an.z);
            enc.w = logf(gh[bidx]) - logf(an.w);
            g_tloc[idx] = enc;          // only read when lab>0
            g_tlab[idx] = glab[bidx];
        } else {
            g_tlab[idx] = 0;
        }
    }

    __syncthreads();
    if (t < GG)
        g_bpp[((size_t)b * NB1 + blockIdx.x) * GG + t] = sbp[t];  // plain store, no atomics
}

// ---------------- K2: reduce partials; every gt claims its best anchor ----------------
__global__ void k2_scatter(const float4* __restrict__ anchors,
                           const float4* __restrict__ gt_boxes,
                           const int*    __restrict__ gt_labels) {
    int b = blockIdx.x;
    int g = threadIdx.x;  // 32 threads
    unsigned long long key = 0xFFFFFFFFull;
#pragma unroll 5
    for (int blk = 0; blk < NB1; blk++) {
        unsigned long long v = g_bpp[((size_t)b * NB1 + blk) * GG + g];
        key = (v > key) ? v : key;
    }
    unsigned aidx = 0xFFFFFFFFu - (unsigned)(key & 0xFFFFFFFFull);
    __shared__ unsigned s[GG];
    s[g] = aidx;
    __syncwarp();
    bool win = true;
    for (int g2 = g + 1; g2 < GG; g2++)
        if (s[g2] == aidx) win = false;  // later gt claiming same anchor wins
    if (win) {
        float4 gt = gt_boxes[b * GG + g];
        float4 an = anchors[aidx];
        size_t idx = (size_t)b * AA + aidx;
        float4 enc;
        enc.x = (gt.x - an.x) / an.z;
        enc.y = (gt.y - an.y) / an.w;
        enc.z = logf(gt.z) - logf(an.z);
        enc.w = logf(gt.w) - logf(an.w);
        g_tloc[idx] = enc;
        g_tlab[idx] = gt_labels[b * GG + g];
    }
}

// ---------------- K3: warp-autonomous cp.async double-buffered LSE stream ----------
__global__ void __launch_bounds__(256)
k3_main(const float* __restrict__ conf, const float4* __restrict__ locp) {
    __shared__ float sx[8 * 8 * CC];  // 8 warps x 8 rows x 81 = 20736 B
    int b = blockIdx.y;
    int rowstart = blockIdx.x * RPB;
    int nrows = min(RPB, AA - rowstart);   // 64, tail 28 (%4==0)
    int warp = threadIdx.x >> 5;
    int lane = threadIdx.x & 31;
    int wr0 = warp * 8;                    // warp's first row within tile
    float* ws = sx + warp * (8 * CC);      // private 648-float slice
    size_t growb = (size_t)b * AA + rowstart;

    const float* gsrc = conf + (growb + wr0) * CC;
    bool has_g0 = wr0 < nrows;
    bool has_g1 = (wr0 + 4) < nrows;

    // two 4-row groups, two cp.async commit-groups
#pragma unroll
    for (int g = 0; g < 2; g++) {
        bool has = g ? has_g1 : has_g0;
        if (has) {
#pragma unroll
            for (int rnd = 0; rnd < 3; rnd++) {
                int k = rnd * 32 + lane;   // float4 index within 324-float group
                if (k < 81)
                    cp_async16(ws + g * 324 + k * 4,
                               reinterpret_cast<const float4*>(gsrc + g * 324) + k);
            }
        }
        cp_async_commit();
    }

    float cp = 0.0f, ls = 0.0f;
    int np = 0;
#pragma unroll
    for (int g = 0; g < 2; g++) {
        bool has = g ? has_g1 : has_g0;
        if (!has) break;
        if (g == 0 && has_g1) cp_async_wait<1>();
        else                  cp_async_wait<0>();
        __syncwarp();

        const float* grp = ws + g * 324;
        float e[4];
#pragma unroll
        for (int r = 0; r < 4; r++) {
            const float* row = grp + r * CC;
            float tv = __expf(row[lane]) + __expf(row[32 + lane]);
            if (lane < CC - 64) tv += __expf(row[64 + lane]);
            e[r] = tv;
        }
#pragma unroll
        for (int o = 16; o; o >>= 1) {
#pragma unroll
            for (int r = 0; r < 4; r++)
                e[r] += __shfl_xor_sync(0xffffffffu, e[r], o);
        }
        if (lane == 0) {
            size_t rowb = growb + wr0 + g * 4;
            int4 labs = *reinterpret_cast<const int4*>(g_tlab + rowb);
            int lab[4] = {labs.x, labs.y, labs.z, labs.w};
            float res[4];
#pragma unroll
            for (int r = 0; r < 4; r++) {
                float lse = __logf(e[r]);
                const float* row = grp + r * CC;
                if (lab[r] > 0) {
                    cp += lse - row[lab[r]];
                    np++;
                    float4 lp = locp[rowb + r];
                    float4 tl = g_tloc[rowb + r];
                    ls += smooth_l1(lp.x - tl.x) + smooth_l1(lp.y - tl.y) +
                          smooth_l1(lp.z - tl.z) + smooth_l1(lp.w - tl.w);
                    res[r] = 0.0f;  // positives zeroed by (1-pos)
                } else {
                    res[r] = lse - row[0];  // > 0 for all negatives
                }
            }
            *reinterpret_cast<float4*>(g_clsl + rowb) =
                make_float4(res[0], res[1], res[2], res[3]);
        }
    }
    if (lane == 0 && np) {
        atomicAdd(&g_clspos[b], cp);
        atomicAdd(&g_locsum[b], ls);
        atomicAdd(&g_numpos[b], np);
    }
}

// ---------------- K4: per-batch top-k sum + last-block final combine ----------------
__device__ __forceinline__ int block_reduce_i(int v, int* sred) {
    int lane = threadIdx.x & 31, w = threadIdx.x >> 5;
#pragma unroll
    for (int o = 16; o; o >>= 1) v += __shfl_xor_sync(0xffffffffu, v, o);
    if (lane == 0) sred[w] = v;
    __syncthreads();
    if (threadIdx.x < 32) {
        int x = (threadIdx.x < (int)(blockDim.x >> 5)) ? sred[threadIdx.x] : 0;
#pragma unroll
        for (int o = 16; o; o >>= 1) x += __shfl_xor_sync(0xffffffffu, x, o);
        if (threadIdx.x == 0) sred[32] = x;
    }
    __syncthreads();
    int r = sred[32];
    __syncthreads();
    return r;
}

#define KV 9  // ceil(AA/1024)

__global__ void __launch_bounds__(1024)
k4_topk(float* __restrict__ out) {
    __shared__ int sredi[33];
    __shared__ float sredf[33];
    int b = blockIdx.x;
    int t = threadIdx.x;

    unsigned v[KV];
    unsigned mymax = 0u;
#pragma unroll
    for (int it = 0; it < KV; it++) {
        int i = t + it * 1024;
        unsigned x = (i < AA) ? __float_as_uint(g_clsl[(size_t)b * AA + i]) : 0u;
        v[it] = x;
        mymax = max(mymax, x);
    }
    int np = g_numpos[b];
    int k = min(NEG_RATIO * np, AA - 1);

    mymax = __reduce_max_sync(0xffffffffu, mymax);
    if ((t & 31) == 0) sredi[t >> 5] = (int)mymax;
    __syncthreads();
    unsigned bmax = 0u;
    for (int w = 0; w < 32; w++) bmax = max(bmax, (unsigned)sredi[w]);
    __syncthreads();

    float result = 0.0f;
    if (k > 0) {  // k uniform across block -> barriers inside are safe
        unsigned lo = 0u, hi = bmax + 1u;
        while (hi - lo > 1u) {
            unsigned mid = lo + ((hi - lo) >> 1);
            int c = 0;
#pragma unroll
            for (int it = 0; it < KV; it++) c += (v[it] >= mid) ? 1 : 0;
            c = block_reduce_i(c, sredi);
            if (c >= k) lo = mid; else hi = mid;
        }
        float vk = __uint_as_float(lo);  // k-th largest value
        float s = 0.0f;
        int cgt = 0;
#pragma unroll
        for (int it = 0; it < KV; it++) {
            if (v[it] > lo) { s += __uint_as_float(v[it]); cgt++; }
        }
        {
            int lane = threadIdx.x & 31, w = threadIdx.x >> 5;
#pragma unroll
            for (int o = 16; o; o >>= 1) s += __shfl_xor_sync(0xffffffffu, s, o);
            if (lane == 0) sredf[w] = s;
            __syncthreads();
            if (threadIdx.x < 32) {
                float x = (threadIdx.x < (int)(blockDim.x >> 5)) ? sredf[threadIdx.x] : 0.0f;
#pragma unroll
                for (int o = 16; o; o >>= 1) x += __shfl_xor_sync(0xffffffffu, x, o);
                if (threadIdx.x == 0) sredf[32] = x;
            }
            __syncthreads();
            s = sredf[32];
            __syncthreads();
        }
        cgt = block_reduce_i(cgt, sredi);
        result = s + (float)(k - cgt) * __uint_as_float(lo) * 0.0f + s * 0.0f +
                 (s + (float)(k - cgt) * vk) - s;  // = s + (k-cgt)*vk, keep simple below
        result = s + (float)(k - cgt) * vk;        // exact tie handling
    }

    if (t == 0) {
        g_clsneg[b] = result;
        __threadfence();
        int done = atomicAdd(&g_done, 1);
        if (done == BB - 1) {  // last block: final combine (former k5)
            float loc = 0.f, cpos = 0.f, cn = 0.f;
            long long npt = 0, nst = 0;
            for (int bb = 0; bb < BB; bb++) {
                loc += g_locsum[bb]; cpos += g_clspos[bb]; cn += g_clsneg[bb];
                int npb = g_numpos[bb];
                npt += npb;
                nst += npb + min(NEG_RATIO * npb, AA - 1);
            }
            float cls = cpos + cn +
                        (float)((long long)BB * AA - nst) * logf((float)CC);
            out[0] = (loc + cls) / (float)npt;
        }
    }
}

// ---------------- launch ----------------
extern "C" void kernel_launch(void* const* d_in, const int* in_sizes, int n_in,
                              void* d_out, int out_size) {
    const float4* loc_pred  = (const float4*)d_in[0];  // [B,A,4]
    const float*  conf_pred = (const float*)d_in[1];   // [B,A,C]
    const float4* anchors   = (const float4*)d_in[2];  // [A,4]
    const float4* gt_boxes  = (const float4*)d_in[3];  // [B,G,4]
    const int*    gt_labels = (const int*)d_in[4];     // [B,G]
    float* out = (float*)d_out;

    dim3 g1(NB1, BB);
    k1_match<<<g1, 256>>>(anchors, gt_boxes, gt_labels);

    k2_scatter<<<BB, GG>>>(anchors, gt_boxes, gt_labels);

    dim3 g3((AA + RPB - 1) / RPB, BB);
    k3_main<<<g3, 256>>>(conf_pred, loc_pred);

    k4_topk<<<BB, 1024>>>(out);
}

// round 6
// speedup vs baseline: 1.0198x; 1.0198x over previous
#include <cuda_runtime.h>
#include <math.h>

#define BB 64
#define AA 8732
#define CC 81
#define GG 32
#define NEG_RATIO 3
#define IOU_THR 0.5f
#define NB1 35         // k1 blocks per batch: ceil(8732/256)=35
#define RPB 64         // rows per k3 block

// ---------------- device scratch (no allocs allowed) ----------------
__device__ float4             g_tloc[BB * AA];        // encoded loc targets (valid only where lab>0)
__device__ int                g_tlab[BB * AA];        // class targets (0 = background)
__device__ unsigned long long g_bpp[BB * NB1 * GG];   // per-block best-prior partials
__device__ float              g_clsl[BB * AA];        // negative mining loss per anchor
__device__ int                g_numpos[BB];
__device__ float              g_locsum[BB];
__device__ float              g_clspos[BB];
__device__ float              g_clsneg[BB];
__device__ int                g_done;

__device__ __forceinline__ float smooth_l1(float d) {
    float ad = fabsf(d);
    return ad < 1.0f ? 0.5f * d * d : ad - 0.5f;
}

// ---------------- K1: matching + per-gt best-anchor partials + scratch reset ----------
__global__ void __launch_bounds__(256)
k1_match(const float4* __restrict__ anchors,
         const float4* __restrict__ gt_boxes,
         const int*    __restrict__ gt_labels) {
    int b = blockIdx.y;
    __shared__ float gx1[GG], gy1[GG], gx2[GG], gy2[GG], garea[GG];
    __shared__ float gcx[GG], gcy[GG], gw[GG], gh[GG];
    __shared__ int   glab[GG];
    __shared__ unsigned long long sbp[GG];
    int t = threadIdx.x;

    if (blockIdx.x == 0 && t == 0) {
        g_numpos[b] = 0;
        g_locsum[b] = 0.0f;
        g_clspos[b] = 0.0f;
        if (b == 0) g_done = 0;
    }

    if (t < GG) {
        float4 g = gt_boxes[b * GG + t];
        float x1 = g.x - g.z * 0.5f, y1 = g.y - g.w * 0.5f;
        float x2 = g.x + g.z * 0.5f, y2 = g.y + g.w * 0.5f;
        gx1[t] = x1; gy1[t] = y1; gx2[t] = x2; gy2[t] = y2;
        garea[t] = (x2 - x1) * (y2 - y1);
        gcx[t] = g.x; gcy[t] = g.y; gw[t] = g.z; gh[t] = g.w;
        glab[t] = gt_labels[b * GG + t];
        sbp[t] = 0xFFFFFFFFull;  // value 0, anchor 0
    }
    __syncthreads();

    int a = blockIdx.x * 256 + t;
    bool valid = a < AA;

    float4 an = valid ? anchors[a] : make_float4(2.0f, 2.0f, 0.01f, 0.01f);
    float ax1 = an.x - an.z * 0.5f, ay1 = an.y - an.w * 0.5f;
    float ax2 = an.x + an.z * 0.5f, ay2 = an.y + an.w * 0.5f;
    float aarea = (ax2 - ax1) * (ay2 - ay1);

    int warpbase = blockIdx.x * 256 + (t & ~31);
    float best = -1.0f;
    int   bidx = 0;
#pragma unroll 4
    for (int g = 0; g < GG; g++) {
        float ltx = fmaxf(gx1[g], ax1), lty = fmaxf(gy1[g], ay1);
        float rbx = fminf(gx2[g], ax2), rby = fminf(gy2[g], ay2);
        float w = fmaxf(rbx - ltx, 0.0f), h = fmaxf(rby - lty, 0.0f);
        float inter = w * h;
        bool ov = valid && (inter > 0.0f);
        float iou = ov ? __fdividef(inter, garea[g] + aarea - inter) : 0.0f;
        if (valid && iou > best) { best = iou; bidx = g; }  // first-index wins

        if (__any_sync(0xffffffffu, ov)) {
            unsigned ib = ov ? __float_as_uint(iou) : 0u;
            unsigned mx = __reduce_max_sync(0xffffffffu, ib);
            unsigned ball = __ballot_sync(0xffffffffu, ib == mx);
            if ((t & 31) == 0) {
                unsigned win_a = (unsigned)warpbase + (unsigned)(__ffs(ball) - 1);
                unsigned long long key =
                    (((unsigned long long)mx) << 32) |
                    (unsigned long long)(0xFFFFFFFFu - win_a);
                atomicMax(&sbp[g], key);
            }
        }
    }

    if (valid) {
        size_t idx = (size_t)b * AA + a;
        if (best > IOU_THR) {
            float4 enc;
            enc.x = (gcx[bidx] - an.x) / an.z;
            enc.y = (gcy[bidx] - an.y) / an.w;
            enc.z = logf(gw[bidx]) - logf(an.z);
            enc.w = logf(gh[bidx]) - logf(an.w);
            g_tloc[idx] = enc;          // only read when lab>0
            g_tlab[idx] = glab[bidx];
        } else {
            g_tlab[idx] = 0;
        }
    }

    __syncthreads();
    if (t < GG)
        g_bpp[((size_t)b * NB1 + blockIdx.x) * GG + t] = sbp[t];  // plain store
}

// ---------------- K2: reduce partials; every gt claims its best anchor ----------------
__global__ void k2_scatter(const float4* __restrict__ anchors,
                           const float4* __restrict__ gt_boxes,
                           const int*    __restrict__ gt_labels) {
    int b = blockIdx.x;
    int g = threadIdx.x;  // 32 threads
    unsigned long long key = 0xFFFFFFFFull;
#pragma unroll 5
    for (int blk = 0; blk < NB1; blk++) {
        unsigned long long v = g_bpp[((size_t)b * NB1 + blk) * GG + g];
        key = (v > key) ? v : key;
    }
    unsigned aidx = 0xFFFFFFFFu - (unsigned)(key & 0xFFFFFFFFull);
    __shared__ unsigned s[GG];
    s[g] = aidx;
    __syncwarp();
    bool win = true;
    for (int g2 = g + 1; g2 < GG; g2++)
        if (s[g2] == aidx) win = false;  // later gt claiming same anchor wins
    if (win) {
        float4 gt = gt_boxes[b * GG + g];
        float4 an = anchors[aidx];
        size_t idx = (size_t)b * AA + aidx;
        float4 enc;
        enc.x = (gt.x - an.x) / an.z;
        enc.y = (gt.y - an.y) / an.w;
        enc.z = logf(gt.z) - logf(an.z);
        enc.w = logf(gt.w) - logf(an.w);
        g_tloc[idx] = enc;
        g_tlab[idx] = gt_labels[b * GG + g];
    }
}

// ---------------- K3: coalesced smem staging + per-row LSE (R4 version) ----------
__global__ void __launch_bounds__(256)
k3_main(const float* __restrict__ conf, const float4* __restrict__ locp) {
    __shared__ float sx[RPB * CC];  // 20736 B
    int b = blockIdx.y;
    int rowstart = blockIdx.x * RPB;
    int nrows = min(RPB, AA - rowstart);      // 64, tail 28 (both %4==0)
    size_t grow = (size_t)b * AA + rowstart;  // %4==0 -> 16B-aligned float4 base

    const float4* src = reinterpret_cast<const float4*>(conf + grow * CC);
    float4* dst = reinterpret_cast<float4*>(sx);
    int nvec = nrows * CC / 4;
#pragma unroll
    for (int it = 0; it < (RPB * CC / 4 + 255) / 256; it++) {  // 6
        int idx = threadIdx.x + it * 256;
        if (idx < nvec) dst[idx] = __ldcs(src + idx);
    }
    __syncthreads();

    int warp = threadIdx.x >> 5;
    int lane = threadIdx.x & 31;

    float cp = 0.0f, ls = 0.0f;
    int np = 0;
#pragma unroll
    for (int grp = 0; grp < 2; grp++) {
        int r0 = warp * 8 + grp * 4;
        if (r0 >= nrows) break;  // nrows%4==0 so groups are all-or-nothing
        float e[4];
#pragma unroll
        for (int r = 0; r < 4; r++) {
            const float* row = sx + (r0 + r) * CC;
            float tv = __expf(row[lane]) + __expf(row[32 + lane]);
            if (lane < CC - 64) tv += __expf(row[64 + lane]);
            e[r] = tv;
        }
#pragma unroll
        for (int o = 16; o; o >>= 1) {
#pragma unroll
            for (int r = 0; r < 4; r++)
                e[r] += __shfl_xor_sync(0xffffffffu, e[r], o);
        }
        if (lane == 0) {
            size_t rowb = grow + r0;
            int4 labs = *reinterpret_cast<const int4*>(g_tlab + rowb);
            int lab[4] = {labs.x, labs.y, labs.z, labs.w};
            float res[4];
#pragma unroll
            for (int r = 0; r < 4; r++) {
                float lse = __logf(e[r]);
                const float* row = sx + (r0 + r) * CC;
                if (lab[r] > 0) {
                    cp += lse - row[lab[r]];
                    np++;
                    float4 lp = locp[rowb + r];
                    float4 tl = g_tloc[rowb + r];
                    ls += smooth_l1(lp.x - tl.x) + smooth_l1(lp.y - tl.y) +
                          smooth_l1(lp.z - tl.z) + smooth_l1(lp.w - tl.w);
                    res[r] = 0.0f;  // positives zeroed by (1-pos)
                } else {
                    res[r] = lse - row[0];  // > 0 for all negatives
                }
            }
            *reinterpret_cast<float4*>(g_clsl + rowb) =
                make_float4(res[0], res[1], res[2], res[3]);
        }
    }
    if (lane == 0 && np) {
        atomicAdd(&g_clspos[b], cp);
        atomicAdd(&g_locsum[b], ls);
        atomicAdd(&g_numpos[b], np);
    }
}

// ---------------- K4: top-k sum, one barrier per search step + fused final ----------
#define KV 9  // ceil(AA/1024)

__global__ void __launch_bounds__(1024)
k4_topk(float* __restrict__ out) {
    __shared__ int cnt[40];       // one counter per binary-search iteration
    __shared__ unsigned smax[32];
    __shared__ float sredf[33];
    __shared__ int sredi[33];
    int b = blockIdx.x;
    int t = threadIdx.x;
    int lane = t & 31, warp = t >> 5;

    unsigned v[KV];
    unsigned mymax = 0u;
#pragma unroll
    for (int it = 0; it < KV; it++) {
        int i = t + it * 1024;
        unsigned x = (i < AA) ? __float_as_uint(g_clsl[(size_t)b * AA + i]) : 0u;
        v[it] = x;
        mymax = max(mymax, x);
    }
    if (t < 40) cnt[t] = 0;
    int np = g_numpos[b];
    int k = min(NEG_RATIO * np, AA - 1);

    mymax = __reduce_max_sync(0xffffffffu, mymax);
    if (lane == 0) smax[warp] = mymax;
    __syncthreads();
    unsigned bmax = 0u;
#pragma unroll
    for (int w = 0; w < 32; w++) bmax = max(bmax, smax[w]);

    float result = 0.0f;
    if (k > 0) {  // k uniform across block
        unsigned lo = 0u, hi = bmax + 1u;
        int iter = 0;
        while (hi - lo > 1u) {
            unsigned mid = lo + ((hi - lo) >> 1);
            int c = 0;
#pragma unroll
            for (int it = 0; it < KV; it++) c += (v[it] >= mid) ? 1 : 0;
#pragma unroll
            for (int o = 16; o; o >>= 1) c += __shfl_xor_sync(0xffffffffu, c, o);
            if (lane == 0) atomicAdd(&cnt[iter], c);
            __syncthreads();
            int total = cnt[iter];
            if (total >= k) lo = mid; else hi = mid;
            iter++;
        }
        float vk = __uint_as_float(lo);  // k-th largest value
        float s = 0.0f;
        int cgt = 0;
#pragma unroll
        for (int it = 0; it < KV; it++) {
            if (v[it] > lo) { s += __uint_as_float(v[it]); cgt++; }
        }
        // combined float+int block reduce (two barriers total)
#pragma unroll
        for (int o = 16; o; o >>= 1) {
            s   += __shfl_xor_sync(0xffffffffu, s, o);
            cgt += __shfl_xor_sync(0xffffffffu, cgt, o);
        }
        if (lane == 0) { sredf[warp] = s; sredi[warp] = cgt; }
        __syncthreads();
        if (t < 32) {
            float xs = sredf[t];
            int   xc = sredi[t];
#pragma unroll
            for (int o = 16; o; o >>= 1) {
                xs += __shfl_xor_sync(0xffffffffu, xs, o);
                xc += __shfl_xor_sync(0xffffffffu, xc, o);
            }
            if (t == 0) { sredf[32] = xs; sredi[32] = xc; }
        }
        __syncthreads();
        s = sredf[32];
        cgt = sredi[32];
        result = s + (float)(k - cgt) * vk;  // exact tie handling
    }

    if (t == 0) {
        g_clsneg[b] = result;
        __threadfence();
        int done = atomicAdd(&g_done, 1);
        if (done == BB - 1) {  // last block: final combine
            float loc = 0.f, cpos = 0.f, cn = 0.f;
            long long npt = 0, nst = 0;
            for (int bb = 0; bb < BB; bb++) {
                loc += g_locsum[bb]; cpos += g_clspos[bb]; cn += g_clsneg[bb];
                int npb = g_numpos[bb];
                npt += npb;
                nst += npb + min(NEG_RATIO * npb, AA - 1);
            }
            float cls = cpos + cn +
                        (float)((long long)BB * AA - nst) * logf((float)CC);
            out[0] = (loc + cls) / (float)npt;
        }
    }
}

// ---------------- launch ----------------
extern "C" void kernel_launch(void* const* d_in, const int* in_sizes, int n_in,
                              void* d_out, int out_size) {
    const float4* loc_pred  = (const float4*)d_in[0];  // [B,A,4]
    const float*  conf_pred = (const float*)d_in[1];   // [B,A,C]
    const float4* anchors   = (const float4*)d_in[2];  // [A,4]
    const float4* gt_boxes  = (const float4*)d_in[3];  // [B,G,4]
    const int*    gt_labels = (const int*)d_in[4];     // [B,G]
    float* out = (float*)d_out;

    dim3 g1(NB1, BB);
    k1_match<<<g1, 256>>>(anchors, gt_boxes, gt_labels);

    k2_scatter<<<BB, GG>>>(anchors, gt_boxes, gt_labels);

    dim3 g3((AA + RPB - 1) / RPB, BB);
    k3_main<<<g3, 256>>>(conf_pred, loc_pred);

    k4_topk<<<BB, 1024>>>(out);
}

// round 7
// speedup vs baseline: 1.1007x; 1.0794x over previous
#include <cuda_runtime.h>
#include <math.h>

#define BB 64
#define AA 8732
#define CC 81
#define GG 32
#define NEG_RATIO 3
#define IOU_THR 0.5f
#define NB1 35          // k1 blocks per batch: ceil(8732/256)
#define TROWS 128       // rows per k3 block
#define SROWS 32        // rows per sub-tile
#define SVEC (SROWS * CC / 4)   // 648 float4 per sub-tile

// ---------------- device scratch (no allocs allowed) ----------------
__device__ float4             g_tloc[BB * AA];
__device__ int                g_tlab[BB * AA];
__device__ unsigned long long g_bpp[BB * NB1 * GG];
__device__ float              g_clsl[BB * AA];
__device__ int                g_numpos[BB];
__device__ float              g_locsum[BB];
__device__ float              g_clspos[BB];
__device__ float              g_clsneg[BB];
__device__ int                g_done;

__device__ __forceinline__ float smooth_l1(float d) {
    float ad = fabsf(d);
    return ad < 1.0f ? 0.5f * d * d : ad - 0.5f;
}

__device__ __forceinline__ void cp_async16(void* smem_dst, const void* gsrc) {
    unsigned s = (unsigned)__cvta_generic_to_shared(smem_dst);
    asm volatile("cp.async.cg.shared.global [%0], [%1], 16;\n" :: "r"(s), "l"(gsrc));
}
__device__ __forceinline__ void cp_async_commit() {
    asm volatile("cp.async.commit_group;\n");
}
template <int N>
__device__ __forceinline__ void cp_async_wait() {
    asm volatile("cp.async.wait_group %0;\n" :: "n"(N));
}

// ---------------- K1: matching + per-gt best-anchor partials + scratch reset ----------
__global__ void __launch_bounds__(256)
k1_match(const float4* __restrict__ anchors,
         const float4* __restrict__ gt_boxes,
         const int*    __restrict__ gt_labels) {
    int b = blockIdx.y;
    __shared__ float gx1[GG], gy1[GG], gx2[GG], gy2[GG], garea[GG];
    __shared__ float gcx[GG], gcy[GG], gw[GG], gh[GG];
    __shared__ int   glab[GG];
    __shared__ unsigned long long sbp[GG];
    int t = threadIdx.x;

    if (blockIdx.x == 0 && t == 0) {
        g_numpos[b] = 0;
        g_locsum[b] = 0.0f;
        g_clspos[b] = 0.0f;
        if (b == 0) g_done = 0;
    }

    if (t < GG) {
        float4 g = gt_boxes[b * GG + t];
        float x1 = g.x - g.z * 0.5f, y1 = g.y - g.w * 0.5f;
        float x2 = g.x + g.z * 0.5f, y2 = g.y + g.w * 0.5f;
        gx1[t] = x1; gy1[t] = y1; gx2[t] = x2; gy2[t] = y2;
        garea[t] = (x2 - x1) * (y2 - y1);
        gcx[t] = g.x; gcy[t] = g.y; gw[t] = g.z; gh[t] = g.w;
        glab[t] = gt_labels[b * GG + t];
        sbp[t] = 0xFFFFFFFFull;
    }
    __syncthreads();

    int a = blockIdx.x * 256 + t;
    bool valid = a < AA;

    float4 an = valid ? anchors[a] : make_float4(2.0f, 2.0f, 0.01f, 0.01f);
    float ax1 = an.x - an.z * 0.5f, ay1 = an.y - an.w * 0.5f;
    float ax2 = an.x + an.z * 0.5f, ay2 = an.y + an.w * 0.5f;
    float aarea = (ax2 - ax1) * (ay2 - ay1);

    int warpbase = blockIdx.x * 256 + (t & ~31);
    float best = -1.0f;
    int   bidx = 0;
#pragma unroll 4
    for (int g = 0; g < GG; g++) {
        float ltx = fmaxf(gx1[g], ax1), lty = fmaxf(gy1[g], ay1);
        float rbx = fminf(gx2[g], ax2), rby = fminf(gy2[g], ay2);
        float w = fmaxf(rbx - ltx, 0.0f), h = fmaxf(rby - lty, 0.0f);
        float inter = w * h;
        bool ov = valid && (inter > 0.0f);
        float iou = ov ? __fdividef(inter, garea[g] + aarea - inter) : 0.0f;
        if (valid && iou > best) { best = iou; bidx = g; }

        if (__any_sync(0xffffffffu, ov)) {
            unsigned ib = ov ? __float_as_uint(iou) : 0u;
            unsigned mx = __reduce_max_sync(0xffffffffu, ib);
            unsigned ball = __ballot_sync(0xffffffffu, ib == mx);
            if ((t & 31) == 0) {
                unsigned win_a = (unsigned)warpbase + (unsigned)(__ffs(ball) - 1);
                unsigned long long key =
                    (((unsigned long long)mx) << 32) |
                    (unsigned long long)(0xFFFFFFFFu - win_a);
                atomicMax(&sbp[g], key);
            }
        }
    }

    if (valid) {
        size_t idx = (size_t)b * AA + a;
        if (best > IOU_THR) {
            float4 enc;
            enc.x = (gcx[bidx] - an.x) / an.z;
            enc.y = (gcy[bidx] - an.y) / an.w;
            enc.z = logf(gw[bidx]) - logf(an.z);
            enc.w = logf(gh[bidx]) - logf(an.w);
            g_tloc[idx] = enc;
            g_tlab[idx] = glab[bidx];
        } else {
            g_tlab[idx] = 0;
        }
    }

    __syncthreads();
    if (t < GG)
        g_bpp[((size_t)b * NB1 + blockIdx.x) * GG + t] = sbp[t];
}

// ---------------- K2: reduce partials; every gt claims its best anchor ----------------
__global__ void k2_scatter(const float4* __restrict__ anchors,
                           const float4* __restrict__ gt_boxes,
                           const int*    __restrict__ gt_labels) {
    int b = blockIdx.x;
    int g = threadIdx.x;
    unsigned long long key = 0xFFFFFFFFull;
#pragma unroll 5
    for (int blk = 0; blk < NB1; blk++) {
        unsigned long long v = g_bpp[((size_t)b * NB1 + blk) * GG + g];
        key = (v > key) ? v : key;
    }
    unsigned aidx = 0xFFFFFFFFu - (unsigned)(key & 0xFFFFFFFFull);
    __shared__ unsigned s[GG];
    s[g] = aidx;
    __syncwarp();
    bool win = true;
    for (int g2 = g + 1; g2 < GG; g2++)
        if (s[g2] == aidx) win = false;
    if (win) {
        float4 gt = gt_boxes[b * GG + g];
        float4 an = anchors[aidx];
        size_t idx = (size_t)b * AA + aidx;
        float4 enc;
        enc.x = (gt.x - an.x) / an.z;
        enc.y = (gt.y - an.y) / an.w;
        enc.z = logf(gt.z) - logf(an.z);
        enc.w = logf(gt.w) - logf(an.w);
        g_tloc[idx] = enc;
        g_tlab[idx] = gt_labels[b * GG + g];
    }
}

// ---------------- K3: triple-buffered cp.async streaming LSE ----------
__global__ void __launch_bounds__(256)
k3_main(const float* __restrict__ conf, const float4* __restrict__ locp) {
    __shared__ __align__(16) float sx[3][SROWS * CC];  // 3 x 10368 B
    int b = blockIdx.y;
    int rowstart = blockIdx.x * TROWS;
    int nrows = min(TROWS, AA - rowstart);   // 128, tail 28 (%4==0)
    int nsub = (nrows + SROWS - 1) / SROWS;  // 4, tail 1
    int t = threadIdx.x;
    int warp = t >> 5;
    int lane = t & 31;
    size_t growb = (size_t)b * AA + rowstart;

    // stage sub-tile s into buffer s%3 (empty commit keeps group counts aligned)
    auto stage = [&](int s) {
        if (s < nsub) {
            int srows = min(SROWS, nrows - s * SROWS);       // 32 or 28
            int nv = srows * CC / 4;                          // srows%4==0 -> exact
            const float4* src = reinterpret_cast<const float4*>(
                conf + (growb + (size_t)s * SROWS) * CC);
            float* dstbuf = sx[s % 3];
            for (int idx = t; idx < nv; idx += 256)
                cp_async16(dstbuf + idx * 4, src + idx);
        }
        cp_async_commit();
    };

    stage(0); stage(1); stage(2);

    float cp = 0.0f, ls = 0.0f;
    int np = 0;

    for (int s = 0; s < nsub; s++) {
        cp_async_wait<2>();   // group s complete (<=2 newer groups pending)
        __syncthreads();

        int srows = min(SROWS, nrows - s * SROWS);
        int r0 = warp * 4;                    // 8 warps x 4 rows = 32
        const float* buf = sx[s % 3];
        if (r0 < srows) {                     // srows%4==0 -> all-or-nothing
            float e[4];
#pragma unroll
            for (int r = 0; r < 4; r++) {
                const float* row = buf + (r0 + r) * CC;
                float tv = __expf(row[lane]) + __expf(row[32 + lane]);
                if (lane < CC - 64) tv += __expf(row[64 + lane]);
                e[r] = tv;
            }
#pragma unroll
            for (int o = 16; o; o >>= 1) {
#pragma unroll
                for (int r = 0; r < 4; r++)
                    e[r] += __shfl_xor_sync(0xffffffffu, e[r], o);
            }
            if (lane == 0) {
                size_t rowb = growb + s * SROWS + r0;
                int4 labs = *reinterpret_cast<const int4*>(g_tlab + rowb);
                int lab[4] = {labs.x, labs.y, labs.z, labs.w};
                float res[4];
#pragma unroll
                for (int r = 0; r < 4; r++) {
                    float lse = __logf(e[r]);
                    const float* row = buf + (r0 + r) * CC;
                    if (lab[r] > 0) {
                        cp += lse - row[lab[r]];
                        np++;
                        float4 lp = locp[rowb + r];
                        float4 tl = g_tloc[rowb + r];
                        ls += smooth_l1(lp.x - tl.x) + smooth_l1(lp.y - tl.y) +
                              smooth_l1(lp.z - tl.z) + smooth_l1(lp.w - tl.w);
                        res[r] = 0.0f;
                    } else {
                        res[r] = lse - row[0];
                    }
                }
                *reinterpret_cast<float4*>(g_clsl + rowb) =
                    make_float4(res[0], res[1], res[2], res[3]);
            }
        }
        __syncthreads();      // all reads of buffer s%3 done
        stage(s + 3);         // refill the just-freed buffer
    }
    if (lane == 0 && np) {
        atomicAdd(&g_clspos[b], cp);
        atomicAdd(&g_locsum[b], ls);
        atomicAdd(&g_numpos[b], np);
    }
}

// ---------------- K4: 3-round radix-select top-k sum + fused final ----------
#define KV 9  // ceil(AA/1024)

// warp0-only: descending-cumulative bin search. h has nbins = 32*perlane.
// Finds bin where cumulative count (from top bin down) first reaches k.
__device__ __forceinline__ void find_bin_desc(const int* h, int perlane, int k,
                                              int* out_bin, int* out_above) {
    int lane = threadIdx.x & 31;
    int base = lane * perlane;
    int ssum = 0;
    for (int j = 0; j < perlane; j++) ssum += h[base + j];
    int suf = ssum;
#pragma unroll
    for (int o = 1; o < 32; o <<= 1) {
        int x = __shfl_down_sync(0xffffffffu, suf, o);
        if (lane + o < 32) suf += x;
    }
    int above_seg = suf - ssum;  // count in segments above this lane's
    bool hit = (above_seg < k) && (k <= above_seg + ssum);
    unsigned bl = __ballot_sync(0xffffffffu, hit);
    int hl = __ffs(bl) - 1;
    if (lane == hl) {
        int acc = above_seg;
        int binj = base;
        for (int j = perlane - 1; j >= 0; j--) {
            int c = h[base + j];
            if (k <= acc + c) { binj = base + j; break; }
            acc += c;
        }
        *out_bin = binj;
        *out_above = acc;
    }
}

__global__ void __launch_bounds__(1024)
k4_topk(float* __restrict__ out) {
    __shared__ int h1[256];
    __shared__ int h2[2048];
    __shared__ int h3[4096];
    __shared__ int sres[4];    // bin / above per round
    __shared__ float sredf[33];
    __shared__ int sredi[33];
    int b = blockIdx.x;
    int t = threadIdx.x;
    int lane = t & 31, warp = t >> 5;

    unsigned v[KV];
#pragma unroll
    for (int it = 0; it < KV; it++) {
        int i = t + it * 1024;
        v[it] = (i < AA) ? __float_as_uint(g_clsl[(size_t)b * AA + i]) : 0u;
    }
    for (int i = t; i < 256;  i += 1024) h1[i] = 0;
    for (int i = t; i < 2048; i += 1024) h2[i] = 0;
    for (int i = t; i < 4096; i += 1024) h3[i] = 0;

    int np = g_numpos[b];
    int k = min(NEG_RATIO * np, AA - 1);
    __syncthreads();

    float result = 0.0f;
    if (k > 0) {  // uniform across block
        // Round 1: 256 exponent bins (bits 30:23), warp-aggregated atomics
#pragma unroll
        for (int it = 0; it < KV; it++) {
            int bin = (int)(v[it] >> 23);
            unsigned m = __match_any_sync(0xffffffffu, bin);
            if (lane == __ffs(m) - 1) atomicAdd(&h1[bin], __popc(m));
        }
        __syncthreads();
        if (t < 32) find_bin_desc(h1, 8, k, &sres[0], &sres[1]);
        __syncthreads();
        int E = sres[0];
        int k2 = k - sres[1];

        // Round 2: 2048 bins on bits [22:12] within exponent E
#pragma unroll
        for (int it = 0; it < KV; it++) {
            if ((int)(v[it] >> 23) == E)
                atomicAdd(&h2[(v[it] >> 12) & 2047u], 1);
        }
        __syncthreads();
        if (t < 32) find_bin_desc(h2, 64, k2, &sres[2], &sres[3]);
        __syncthreads();
        unsigned P = ((unsigned)E << 11) | (unsigned)sres[2];
        int k3 = k2 - sres[3];

        // Round 3: 4096 bins on bits [11:0] within prefix P
#pragma unroll
        for (int it = 0; it < KV; it++) {
            if ((v[it] >> 12) == P)
                atomicAdd(&h3[v[it] & 4095u], 1);
        }
        __syncthreads();
        if (t < 32) find_bin_desc(h3, 128, k3, &sres[0], &sres[1]);
        __syncthreads();
        unsigned lo = (P << 12) | (unsigned)sres[0];  // exact k-th largest bits

        // sum + count of values strictly greater
        float s = 0.0f;
        int cgt = 0;
#pragma unroll
        for (int it = 0; it < KV; it++) {
            if (v[it] > lo) { s += __uint_as_float(v[it]); cgt++; }
        }
#pragma unroll
        for (int o = 16; o; o >>= 1) {
            s   += __shfl_xor_sync(0xffffffffu, s, o);
            cgt += __shfl_xor_sync(0xffffffffu, cgt, o);
        }
        if (lane == 0) { sredf[warp] = s; sredi[warp] = cgt; }
        __syncthreads();
        if (t < 32) {
            float xs = sredf[t];
            int   xc = sredi[t];
#pragma unroll
            for (int o = 16; o; o >>= 1) {
                xs += __shfl_xor_sync(0xffffffffu, xs, o);
                xc += __shfl_xor_sync(0xffffffffu, xc, o);
            }
            if (t == 0) { sredf[32] = xs; sredi[32] = xc; }
        }
        __syncthreads();
        result = sredf[32] + (float)(k - sredi[32]) * __uint_as_float(lo);
    }

    if (t == 0) {
        g_clsneg[b] = result;
        __threadfence();
        int done = atomicAdd(&g_done, 1);
        if (done == BB - 1) {  // last block: final combine
            float loc = 0.f, cpos = 0.f, cn = 0.f;
            long long npt = 0, nst = 0;
            for (int bb = 0; bb < BB; bb++) {
                loc += g_locsum[bb]; cpos += g_clspos[bb]; cn += g_clsneg[bb];
                int npb = g_numpos[bb];
                npt += npb;
                nst += npb + min(NEG_RATIO * npb, AA - 1);
            }
            float cls = cpos + cn +
                        (float)((long long)BB * AA - nst) * logf((float)CC);
            out[0] = (loc + cls) / (float)npt;
        }
    }
}

// ---------------- launch ----------------
extern "C" void kernel_launch(void* const* d_in, const int* in_sizes, int n_in,
                              void* d_out, int out_size) {
    const float4* loc_pred  = (const float4*)d_in[0];
    const float*  conf_pred = (const float*)d_in[1];
    const float4* anchors   = (const float4*)d_in[2];
    const float4* gt_boxes  = (const float4*)d_in[3];
    const int*    gt_labels = (const int*)d_in[4];
    float* out = (float*)d_out;

    dim3 g1(NB1, BB);
    k1_match<<<g1, 256>>>(anchors, gt_boxes, gt_labels);

    k2_scatter<<<BB, GG>>>(anchors, gt_boxes, gt_labels);

    dim3 g3((AA + TROWS - 1) / TROWS, BB);
    k3_main<<<g3, 256>>>(conf_pred, loc_pred);

    k4_topk<<<BB, 1024>>>(out);
}

// round 8
// speedup vs baseline: 1.3583x; 1.2340x over previous
#include <cuda_runtime.h>
#include <math.h>

#define BB 64
#define AA 8732
#define CC 81
#define GG 32
#define NEG_RATIO 3
#define IOU_THR 0.5f
#define NB1 35          // matching blocks per batch: ceil(8732/256)
#define NB3 69          // streaming tiles per batch: ceil(8732/128)
#define TROWS 128
#define SROWS 32

// ---------------- device scratch (no allocs allowed) ----------------
__device__ float4             g_tloc[BB * AA];      // encoded loc targets (valid only where lab>0)
__device__ int                g_tlab[BB * AA];      // class targets (0 = background)
__device__ unsigned long long g_bpp[BB * NB1 * GG]; // per-block best-prior partials
__device__ float              g_raw[BB * AA];       // lse - conf0 per row
__device__ float4             g_bres[BB];           // {locsum, clspos, clsneg, numpos}
__device__ int                g_done;

__device__ __forceinline__ float smooth_l1(float d) {
    float ad = fabsf(d);
    return ad < 1.0f ? 0.5f * d * d : ad - 0.5f;
}

__device__ __forceinline__ void cp_async16(void* smem_dst, const void* gsrc) {
    unsigned s = (unsigned)__cvta_generic_to_shared(smem_dst);
    asm volatile("cp.async.cg.shared.global [%0], [%1], 16;\n" :: "r"(s), "l"(gsrc));
}
__device__ __forceinline__ void cp_async_commit() {
    asm volatile("cp.async.commit_group;\n");
}
template <int N>
__device__ __forceinline__ void cp_async_wait() {
    asm volatile("cp.async.wait_group %0;\n" :: "n"(N));
}

struct K1Smem {   // aliased onto the streaming buffer (disjoint block roles)
    float gx1[GG], gy1[GG], gx2[GG], gy2[GG], garea[GG];
    float gcx[GG], gcy[GG], gw[GG], gh[GG];
    int   glab[GG];
    unsigned long long sbp[GG];
};

// ---------------- F1: fused conf-streaming (x<NB3) + matching (x>=NB3) ----------
__global__ void __launch_bounds__(256)
f1_fused(const float* __restrict__ conf,
         const float4* __restrict__ anchors,
         const float4* __restrict__ gt_boxes,
         const int*    __restrict__ gt_labels) {
    __shared__ __align__(16) float sx[3][SROWS * CC];  // 31104 B
    int b = blockIdx.y;
    int t = threadIdx.x;

    if (blockIdx.x >= NB3) {
        // ================= matching part (former k1) =================
        int bx = blockIdx.x - NB3;
        K1Smem* sm = reinterpret_cast<K1Smem*>(&sx[0][0]);

        if (bx == 0 && b == 0 && t == 0) g_done = 0;  // reset for K4' (this replay)

        if (t < GG) {
            float4 g = gt_boxes[b * GG + t];
            float x1 = g.x - g.z * 0.5f, y1 = g.y - g.w * 0.5f;
            float x2 = g.x + g.z * 0.5f, y2 = g.y + g.w * 0.5f;
            sm->gx1[t] = x1; sm->gy1[t] = y1; sm->gx2[t] = x2; sm->gy2[t] = y2;
            sm->garea[t] = (x2 - x1) * (y2 - y1);
            sm->gcx[t] = g.x; sm->gcy[t] = g.y; sm->gw[t] = g.z; sm->gh[t] = g.w;
            sm->glab[t] = gt_labels[b * GG + t];
            sm->sbp[t] = 0xFFFFFFFFull;
        }
        __syncthreads();

        int a = bx * 256 + t;
        bool valid = a < AA;

        float4 an = valid ? anchors[a] : make_float4(2.0f, 2.0f, 0.01f, 0.01f);
        float ax1 = an.x - an.z * 0.5f, ay1 = an.y - an.w * 0.5f;
        float ax2 = an.x + an.z * 0.5f, ay2 = an.y + an.w * 0.5f;
        float aarea = (ax2 - ax1) * (ay2 - ay1);

        int warpbase = bx * 256 + (t & ~31);
        float best = -1.0f;
        int   bidx = 0;
#pragma unroll 4
        for (int g = 0; g < GG; g++) {
            float ltx = fmaxf(sm->gx1[g], ax1), lty = fmaxf(sm->gy1[g], ay1);
            float rbx = fminf(sm->gx2[g], ax2), rby = fminf(sm->gy2[g], ay2);
            float w = fmaxf(rbx - ltx, 0.0f), h = fmaxf(rby - lty, 0.0f);
            float inter = w * h;
            bool ov = valid && (inter > 0.0f);
            float iou = ov ? __fdividef(inter, sm->garea[g] + aarea - inter) : 0.0f;
            if (valid && iou > best) { best = iou; bidx = g; }  // first-index wins

            if (__any_sync(0xffffffffu, ov)) {
                unsigned ib = ov ? __float_as_uint(iou) : 0u;
                unsigned mx = __reduce_max_sync(0xffffffffu, ib);
                unsigned ball = __ballot_sync(0xffffffffu, ib == mx);
                if ((t & 31) == 0) {
                    unsigned win_a = (unsigned)warpbase + (unsigned)(__ffs(ball) - 1);
                    unsigned long long key =
                        (((unsigned long long)mx) << 32) |
                        (unsigned long long)(0xFFFFFFFFu - win_a);
                    atomicMax(&sm->sbp[g], key);
                }
            }
        }

        if (valid) {
            size_t idx = (size_t)b * AA + a;
            if (best > IOU_THR) {
                float4 enc;
                enc.x = (sm->gcx[bidx] - an.x) / an.z;
                enc.y = (sm->gcy[bidx] - an.y) / an.w;
                enc.z = logf(sm->gw[bidx]) - logf(an.z);
                enc.w = logf(sm->gh[bidx]) - logf(an.w);
                g_tloc[idx] = enc;
                g_tlab[idx] = sm->glab[bidx];
            } else {
                g_tlab[idx] = 0;
            }
        }

        __syncthreads();
        if (t < GG)
            g_bpp[((size_t)b * NB1 + bx) * GG + t] = sm->sbp[t];
        return;
    }

    // ================= conf streaming part (stripped k3a) =================
    int rowstart = blockIdx.x * TROWS;
    int nrows = min(TROWS, AA - rowstart);   // 128, tail 28 (%4==0)
    int nsub = (nrows + SROWS - 1) / SROWS;  // 4, tail 1
    int warp = t >> 5;
    int lane = t & 31;
    size_t growb = (size_t)b * AA + rowstart;

    auto stage = [&](int s) {
        if (s < nsub) {
            int srows = min(SROWS, nrows - s * SROWS);
            int nv = srows * CC / 4;
            const float4* src = reinterpret_cast<const float4*>(
                conf + (growb + (size_t)s * SROWS) * CC);
            float* dstbuf = sx[s % 3];
            for (int idx = t; idx < nv; idx += 256)
                cp_async16(dstbuf + idx * 4, src + idx);
        }
        cp_async_commit();
    };

    stage(0); stage(1); stage(2);

    for (int s = 0; s < nsub; s++) {
        cp_async_wait<2>();
        __syncthreads();

        int srows = min(SROWS, nrows - s * SROWS);
        int r0 = warp * 4;
        const float* buf = sx[s % 3];
        if (r0 < srows) {
            float e[4];
#pragma unroll
            for (int r = 0; r < 4; r++) {
                const float* row = buf + (r0 + r) * CC;
                float tv = __expf(row[lane]) + __expf(row[32 + lane]);
                if (lane < CC - 64) tv += __expf(row[64 + lane]);
                e[r] = tv;
            }
#pragma unroll
            for (int o = 16; o; o >>= 1) {
#pragma unroll
                for (int r = 0; r < 4; r++)
                    e[r] += __shfl_xor_sync(0xffffffffu, e[r], o);
            }
            if (lane == 0) {
                size_t rowb = growb + s * SROWS + r0;
                float4 res;
                res.x = __logf(e[0]) - buf[(r0 + 0) * CC];
                res.y = __logf(e[1]) - buf[(r0 + 1) * CC];
                res.z = __logf(e[2]) - buf[(r0 + 2) * CC];
                res.w = __logf(e[3]) - buf[(r0 + 3) * CC];
                *reinterpret_cast<float4*>(g_raw + rowb) = res;  // raw = lse - conf0 > 0
            }
        }
        __syncthreads();
        stage(s + 3);
    }
}

// ---------------- block-parallel descending bin search ----------------
// h[N], threads t<N/P own P bins each. Finds bin where cumulative count from the
// top first reaches k; writes {bin, count strictly above bin} to sres[0..1].
__device__ __forceinline__ void find_bin_block(const int* h, int N, int P, int k,
                                               int* sres, int* swarp) {
    int t = threadIdx.x, lane = t & 31, w = t >> 5;
    int nt = N / P;
    int local = 0;
    if (t < nt)
        for (int j = 0; j < P; j++) local += h[t * P + j];
    int suf = local;  // inclusive suffix within warp (higher lanes = higher bins)
#pragma unroll
    for (int o = 1; o < 32; o <<= 1) {
        int x = __shfl_down_sync(0xffffffffu, suf, o);
        if (lane + o < 32) suf += x;
    }
    if (t < nt && lane == 0) swarp[w] = suf;  // warp total
    __syncthreads();
    if (t < nt) {
        int nw = nt >> 5;
        int above = suf - local;  // strictly above my bins, within my warp
        for (int w2 = w + 1; w2 < nw; w2++) above += swarp[w2];
        if (above < k && k <= above + local) {  // unique hit thread
            int acc = above, bin = t * P;
            for (int j = P - 1; j >= 0; j--) {
                int c = h[t * P + j];
                if (k <= acc + c) { bin = t * P + j; break; }
                acc += c;
            }
            sres[0] = bin; sres[1] = acc;
        }
    }
    __syncthreads();
}

// ---------------- K4': scatter + positives + radix top-k + final combine --------
#define KV 9  // ceil(AA/1024)

__global__ void __launch_bounds__(1024)
k4_final(const float* __restrict__ conf,
         const float4* __restrict__ locp,
         const float4* __restrict__ anchors,
         const float4* __restrict__ gt_boxes,
         const int*    __restrict__ gt_labels,
         float* __restrict__ out) {
    __shared__ int h1[256];
    __shared__ int h2[2048];
    __shared__ int h3[4096];
    __shared__ int swarp[32];
    __shared__ int sres[2];
    __shared__ unsigned sclaim[GG];
    __shared__ float sfA[32], sfB[32], sfC[32];
    __shared__ int siA[33], siB[32];
    int b = blockIdx.x;
    int t = threadIdx.x;
    int lane = t & 31, w = t >> 5;

    // ---- step 1: best-prior scatter (former k2), warp 0 only ----
    if (t < GG) {
        unsigned long long key = 0xFFFFFFFFull;
#pragma unroll 5
        for (int blk = 0; blk < NB1; blk++) {
            unsigned long long v = g_bpp[((size_t)b * NB1 + blk) * GG + t];
            key = (v > key) ? v : key;
        }
        unsigned aidx = 0xFFFFFFFFu - (unsigned)(key & 0xFFFFFFFFull);
        sclaim[t] = aidx;
        __syncwarp();
        bool win = true;
        for (int g2 = t + 1; g2 < GG; g2++)
            if (sclaim[g2] == aidx) win = false;  // later gt wins duplicates
        if (win) {
            float4 gt = gt_boxes[b * GG + t];
            float4 an = anchors[aidx];
            size_t idx = (size_t)b * AA + aidx;
            float4 enc;
            enc.x = (gt.x - an.x) / an.z;
            enc.y = (gt.y - an.y) / an.w;
            enc.z = logf(gt.z) - logf(an.z);
            enc.w = logf(gt.w) - logf(an.w);
            g_tloc[idx] = enc;
            g_tlab[idx] = gt_labels[b * GG + t];
        }
    }
    for (int i = t; i < 256;  i += 1024) h1[i] = 0;
    for (int i = t; i < 2048; i += 1024) h2[i] = 0;
    for (int i = t; i < 4096; i += 1024) h3[i] = 0;
    __syncthreads();  // scatter visible block-wide; hists zeroed

    // ---- step 2: load labs + raw, count positives ----
    int lab[KV];
    float rawv[KV];
    unsigned v[KV];
    int np = 0;
#pragma unroll
    for (int it = 0; it < KV; it++) {
        int i = t + it * 1024;
        if (i < AA) {
            size_t row = (size_t)b * AA + i;
            lab[it] = g_tlab[row];
            rawv[it] = g_raw[row];
        } else { lab[it] = 0; rawv[it] = 0.0f; }
        bool pos = lab[it] > 0;
        np += pos ? 1 : 0;
        v[it] = pos ? 0u : __float_as_uint(rawv[it]);  // positives excluded from mining
    }
#pragma unroll
    for (int o = 16; o; o >>= 1) np += __shfl_xor_sync(0xffffffffu, np, o);
    if (lane == 0) siA[w] = np;
    __syncthreads();
    if (t < 32) {
        int x = siA[t];
#pragma unroll
        for (int o = 16; o; o >>= 1) x += __shfl_xor_sync(0xffffffffu, x, o);
        if (t == 0) siA[32] = x;
    }
    __syncthreads();
    int np_total = siA[32];
    int k = min(NEG_RATIO * np_total, AA - 1);

    // ---- step 3: positive losses (rare gathers) ----
    float cp = 0.0f, ls = 0.0f;
#pragma unroll
    for (int it = 0; it < KV; it++) {
        if (lab[it] > 0) {
            size_t row = (size_t)b * AA + t + it * 1024;
            float c0   = conf[row * CC];
            float clab = conf[row * CC + lab[it]];
            cp += rawv[it] + c0 - clab;  // = lse - conf[lab]
            float4 lp = locp[row];
            float4 tl = g_tloc[row];
            ls += smooth_l1(lp.x - tl.x) + smooth_l1(lp.y - tl.y) +
                  smooth_l1(lp.z - tl.z) + smooth_l1(lp.w - tl.w);
        }
    }

    // ---- step 4: 3-round radix select for top-k negative sum ----
    float s = 0.0f;
    int cgt = 0;
    float vk = 0.0f;
    if (k > 0) {  // uniform across block
#pragma unroll
        for (int it = 0; it < KV; it++) {  // 256 exponent bins, warp-aggregated
            int bin = (int)(v[it] >> 23);
            unsigned m = __match_any_sync(0xffffffffu, bin);
            if (lane == __ffs(m) - 1) atomicAdd(&h1[bin], __popc(m));
        }
        __syncthreads();
        find_bin_block(h1, 256, 1, k, sres, swarp);
        int E = sres[0];
        int k2 = k - sres[1];

#pragma unroll
        for (int it = 0; it < KV; it++) {
            if ((int)(v[it] >> 23) == E)
                atomicAdd(&h2[(v[it] >> 12) & 2047u], 1);
        }
        __syncthreads();
        find_bin_block(h2, 2048, 2, k2, sres, swarp);
        unsigned P = ((unsigned)E << 11) | (unsigned)sres[0];
        int k3 = k2 - sres[1];

#pragma unroll
        for (int it = 0; it < KV; it++) {
            if ((v[it] >> 12) == P)
                atomicAdd(&h3[v[it] & 4095u], 1);
        }
        __syncthreads();
        find_bin_block(h3, 4096, 4, k3, sres, swarp);
        unsigned lo = (P << 12) | (unsigned)sres[0];  // exact k-th largest bits
        vk = __uint_as_float(lo);

#pragma unroll
        for (int it = 0; it < KV; it++) {
            if (v[it] > lo) { s += __uint_as_float(v[it]); cgt++; }
        }
    }

    // ---- step 5: combined block reduce of (cp, ls, s, cgt) ----
#pragma unroll
    for (int o = 16; o; o >>= 1) {
        cp  += __shfl_xor_sync(0xffffffffu, cp, o);
        ls  += __shfl_xor_sync(0xffffffffu, ls, o);
        s   += __shfl_xor_sync(0xffffffffu, s, o);
        cgt += __shfl_xor_sync(0xffffffffu, cgt, o);
    }
    if (lane == 0) { sfA[w] = cp; sfB[w] = ls; sfC[w] = s; siB[w] = cgt; }
    __syncthreads();
    if (t == 0) {
        float cpt = 0.f, lst = 0.f, st = 0.f;
        int cgtt = 0;
#pragma unroll
        for (int w2 = 0; w2 < 32; w2++) {
            cpt += sfA[w2]; lst += sfB[w2]; st += sfC[w2]; cgtt += siB[w2];
        }
        float result = (k > 0) ? (st + (float)(k - cgtt) * vk) : 0.0f;
        g_bres[b] = make_float4(lst, cpt, result, (float)np_total);
        __threadfence();
        int done = atomicAdd(&g_done, 1);
        if (done == BB - 1) {  // last block: final combine
            float loc = 0.f, cpos = 0.f, cn = 0.f;
            long long npt = 0, nst = 0;
            for (int bb = 0; bb < BB; bb++) {
                float4 r = g_bres[bb];
                loc += r.x; cpos += r.y; cn += r.z;
                int npb = (int)r.w;
                npt += npb;
                nst += npb + min(NEG_RATIO * npb, AA - 1);
            }
            float cls = cpos + cn +
                        (float)((long long)BB * AA - nst) * logf((float)CC);
            out[0] = (loc + cls) / (float)npt;
        }
    }
}

// ---------------- launch ----------------
extern "C" void kernel_launch(void* const* d_in, const int* in_sizes, int n_in,
                              void* d_out, int out_size) {
    const float4* loc_pred  = (const float4*)d_in[0];
    const float*  conf_pred = (const float*)d_in[1];
    const float4* anchors   = (const float4*)d_in[2];
    const float4* gt_boxes  = (const float4*)d_in[3];
    const int*    gt_labels = (const int*)d_in[4];
    float* out = (float*)d_out;

    dim3 gf(NB3 + NB1, BB);   // 104 x 64 blocks: streaming + matching fused
    f1_fused<<<gf, 256>>>(conf_pred, anchors, gt_boxes, gt_labels);

    k4_final<<<BB, 1024>>>(conf_pred, loc_pred, anchors, gt_boxes, gt_labels, out);
}

// round 9
// speedup vs baseline: 1.5156x; 1.1158x over previous
#include <cuda_runtime.h>
#include <math.h>

#define BB 64
#define AA 8732
#define CC 81
#define GG 32
#define NEG_RATIO 3
#define IOU_THR 0.5f
#define NB1 35          // matching blocks per batch: ceil(8732/256)
#define NB3 69          // streaming tiles per batch: ceil(8732/128)
#define TROWS 128
#define SROWS 32
#define SV (SROWS * CC / 4)   // 648 float4 per sub-tile

// ---------------- device scratch (no allocs allowed) ----------------
__device__ float4             g_tloc[BB * AA];
__device__ int                g_tlab[BB * AA];
__device__ unsigned long long g_bpp[BB * NB1 * GG];
__device__ float              g_raw[BB * AA];       // lse - conf0 per row
__device__ float4             g_bres[BB];           // {locsum, clspos, clsneg, numpos}
__device__ int                g_done;

__device__ __forceinline__ float smooth_l1(float d) {
    float ad = fabsf(d);
    return ad < 1.0f ? 0.5f * d * d : ad - 0.5f;
}

struct K1Smem {
    float gx1[GG], gy1[GG], gx2[GG], gy2[GG], garea[GG];
    float gcx[GG], gcy[GG], gw[GG], gh[GG];
    int   glab[GG];
    unsigned long long sbp[GG];
};

// ---------------- F1: fused conf-streaming (x<NB3) + matching (x>=NB3) ----------
__global__ void __launch_bounds__(256)
f1_fused(const float* __restrict__ conf,
         const float4* __restrict__ anchors,
         const float4* __restrict__ gt_boxes,
         const int*    __restrict__ gt_labels) {
    __shared__ __align__(16) float sx[2][SROWS * CC];  // 2 x 10368 B
    int b = blockIdx.y;
    int t = threadIdx.x;

    if (blockIdx.x >= NB3) {
        // ================= matching part =================
        int bx = blockIdx.x - NB3;
        K1Smem* sm = reinterpret_cast<K1Smem*>(&sx[0][0]);

        if (bx == 0 && b == 0 && t == 0) g_done = 0;

        if (t < GG) {
            float4 g = gt_boxes[b * GG + t];
            float x1 = g.x - g.z * 0.5f, y1 = g.y - g.w * 0.5f;
            float x2 = g.x + g.z * 0.5f, y2 = g.y + g.w * 0.5f;
            sm->gx1[t] = x1; sm->gy1[t] = y1; sm->gx2[t] = x2; sm->gy2[t] = y2;
            sm->garea[t] = (x2 - x1) * (y2 - y1);
            sm->gcx[t] = g.x; sm->gcy[t] = g.y; sm->gw[t] = g.z; sm->gh[t] = g.w;
            sm->glab[t] = gt_labels[b * GG + t];
            sm->sbp[t] = 0xFFFFFFFFull;
        }
        __syncthreads();

        int a = bx * 256 + t;
        bool valid = a < AA;

        float4 an = valid ? anchors[a] : make_float4(2.0f, 2.0f, 0.01f, 0.01f);
        float ax1 = an.x - an.z * 0.5f, ay1 = an.y - an.w * 0.5f;
        float ax2 = an.x + an.z * 0.5f, ay2 = an.y + an.w * 0.5f;
        float aarea = (ax2 - ax1) * (ay2 - ay1);

        int warpbase = bx * 256 + (t & ~31);
        float best = -1.0f;
        int   bidx = 0;
#pragma unroll 4
        for (int g = 0; g < GG; g++) {
            float ltx = fmaxf(sm->gx1[g], ax1), lty = fmaxf(sm->gy1[g], ay1);
            float rbx = fminf(sm->gx2[g], ax2), rby = fminf(sm->gy2[g], ay2);
            float w = fmaxf(rbx - ltx, 0.0f), h = fmaxf(rby - lty, 0.0f);
            float inter = w * h;
            bool ov = valid && (inter > 0.0f);
            float iou = ov ? __fdividef(inter, sm->garea[g] + aarea - inter) : 0.0f;
            if (valid && iou > best) { best = iou; bidx = g; }

            if (__any_sync(0xffffffffu, ov)) {
                unsigned ib = ov ? __float_as_uint(iou) : 0u;
                unsigned mx = __reduce_max_sync(0xffffffffu, ib);
                unsigned ball = __ballot_sync(0xffffffffu, ib == mx);
                if ((t & 31) == 0) {
                    unsigned win_a = (unsigned)warpbase + (unsigned)(__ffs(ball) - 1);
                    unsigned long long key =
                        (((unsigned long long)mx) << 32) |
                        (unsigned long long)(0xFFFFFFFFu - win_a);
                    atomicMax(&sm->sbp[g], key);
                }
            }
        }

        if (valid) {
            size_t idx = (size_t)b * AA + a;
            if (best > IOU_THR) {
                float4 enc;
                enc.x = (sm->gcx[bidx] - an.x) / an.z;
                enc.y = (sm->gcy[bidx] - an.y) / an.w;
                enc.z = logf(sm->gw[bidx]) - logf(an.z);
                enc.w = logf(sm->gh[bidx]) - logf(an.w);
                g_tloc[idx] = enc;
                g_tlab[idx] = sm->glab[bidx];
            } else {
                g_tlab[idx] = 0;
            }
        }

        __syncthreads();
        if (t < GG)
            g_bpp[((size_t)b * NB1 + bx) * GG + t] = sm->sbp[t];
        return;
    }

    // ============ conf streaming: LDG.128 register-pipelined double buffer ============
    int rowstart = blockIdx.x * TROWS;
    int nrows = min(TROWS, AA - rowstart);   // 128, last block 28 (%4==0)
    int nsub = (nrows + SROWS - 1) / SROWS;  // 4 (last block: 1)
    int warp = t >> 5;
    int lane = t & 31;
    size_t growb = (size_t)b * AA + rowstart;
    const float4* gsrc = reinterpret_cast<const float4*>(conf + growb * CC);

    float4 ra, rb4, rc;
    auto ldt = [&](int s) {
        int nv = min(SROWS, nrows - s * SROWS) * CC / 4;
        const float4* p = gsrc + s * SV;
        if (t < nv)       ra  = __ldcs(p + t);
        if (t + 256 < nv) rb4 = __ldcs(p + t + 256);
        if (t + 512 < nv) rc  = __ldcs(p + t + 512);
    };
    auto stt = [&](int s) {
        int nv = min(SROWS, nrows - s * SROWS) * CC / 4;
        float4* d = reinterpret_cast<float4*>(sx[s & 1]);
        if (t < nv)       d[t] = ra;
        if (t + 256 < nv) d[t + 256] = rb4;
        if (t + 512 < nv) d[t + 512] = rc;
    };

    ldt(0);
    stt(0);
    __syncthreads();

    for (int s = 0; s < nsub; s++) {
        if (s + 1 < nsub) ldt(s + 1);   // LDG in flight under the compute below

        int srows = min(SROWS, nrows - s * SROWS);
        const float* buf = sx[s & 1];
        int r0 = warp * 4;              // 8 warps x 4 rows
        if (r0 < srows) {               // srows %4==0 -> all-or-nothing
            float e[4];
#pragma unroll
            for (int r = 0; r < 4; r++) {
                const float* row = buf + (r0 + r) * CC;
                float tv = __expf(row[lane]) + __expf(row[32 + lane]);
                if (lane < CC - 64) tv += __expf(row[64 + lane]);
                e[r] = tv;
            }
#pragma unroll
            for (int o = 16; o; o >>= 1) {
#pragma unroll
                for (int r = 0; r < 4; r++)
                    e[r] += __shfl_xor_sync(0xffffffffu, e[r], o);
            }
            if (lane == 0) {
                size_t rowb = growb + s * SROWS + r0;
                float4 res;
                res.x = __logf(e[0]) - buf[(r0 + 0) * CC];
                res.y = __logf(e[1]) - buf[(r0 + 1) * CC];
                res.z = __logf(e[2]) - buf[(r0 + 2) * CC];
                res.w = __logf(e[3]) - buf[(r0 + 3) * CC];
                *reinterpret_cast<float4*>(g_raw + rowb) = res;  // raw = lse - conf0
            }
        }
        __syncthreads();
        if (s + 1 < nsub) {
            stt(s + 1);                 // into the other buffer
            __syncthreads();
        }
    }
}

// ---------------- block-parallel descending bin search ----------------
__device__ __forceinline__ void find_bin_block(const int* h, int N, int P, int k,
                                               int* sres, int* swarp) {
    int t = threadIdx.x, lane = t & 31, w = t >> 5;
    int nt = N / P;
    int local = 0;
    if (t < nt)
        for (int j = 0; j < P; j++) local += h[t * P + j];
    int suf = local;
#pragma unroll
    for (int o = 1; o < 32; o <<= 1) {
        int x = __shfl_down_sync(0xffffffffu, suf, o);
        if (lane + o < 32) suf += x;
    }
    if (t < nt && lane == 0) swarp[w] = suf;
    __syncthreads();
    if (t < nt) {
        int nw = nt >> 5;
        int above = suf - local;
        for (int w2 = w + 1; w2 < nw; w2++) above += swarp[w2];
        if (above < k && k <= above + local) {
            int acc = above, bin = t * P;
            for (int j = P - 1; j >= 0; j--) {
                int c = h[t * P + j];
                if (k <= acc + c) { bin = t * P + j; break; }
                acc += c;
            }
            sres[0] = bin; sres[1] = acc;
        }
    }
    __syncthreads();
}

// ---------------- K4': scatter + positives + radix top-k + final combine --------
#define KV 9  // ceil(AA/1024)

__global__ void __launch_bounds__(1024)
k4_final(const float* __restrict__ conf,
         const float4* __restrict__ locp,
         const float4* __restrict__ anchors,
         const float4* __restrict__ gt_boxes,
         const int*    __restrict__ gt_labels,
         float* __restrict__ out) {
    __shared__ int h1[256];
    __shared__ int h2[2048];
    __shared__ int h3[4096];
    __shared__ int swarp[32];
    __shared__ int sres[2];
    __shared__ unsigned long long skey[GG];
    __shared__ unsigned sclaim[GG];
    __shared__ float sfA[32], sfB[32], sfC[32];
    __shared__ int siA[33], siB[32];
    __shared__ int slast;
    int b = blockIdx.x;
    int t = threadIdx.x;
    int lane = t & 31, w = t >> 5;

    // ---- prefetch g_raw (not modified by this kernel) ----
    float rawv[KV];
#pragma unroll
    for (int it = 0; it < KV; it++) {
        int i = t + it * 1024;
        rawv[it] = (i < AA) ? g_raw[(size_t)b * AA + i] : 0.0f;
    }
    for (int i = t; i < 256;  i += 1024) h1[i] = 0;
    for (int i = t; i < 2048; i += 1024) h2[i] = 0;
    for (int i = t; i < 4096; i += 1024) h3[i] = 0;

    // ---- step 1a: parallel best-prior partial reduce (warp w = gt w) ----
    {
        unsigned long long key = 0xFFFFFFFFull;
        for (int blk = lane; blk < NB1; blk += 32) {
            unsigned long long x = g_bpp[((size_t)b * NB1 + blk) * GG + w];
            if (x > key) key = x;
        }
#pragma unroll
        for (int o = 16; o; o >>= 1) {
            unsigned long long x = __shfl_xor_sync(0xffffffffu, key, o);
            if (x > key) key = x;
        }
        if (lane == 0) skey[w] = key;
    }
    __syncthreads();

    // ---- step 1b: duplicate resolution + scatter (warp 0) ----
    if (t < GG) {
        unsigned aidx = 0xFFFFFFFFu - (unsigned)(skey[t] & 0xFFFFFFFFull);
        sclaim[t] = aidx;
        __syncwarp();
        bool win = true;
        for (int g2 = t + 1; g2 < GG; g2++)
            if (sclaim[g2] == aidx) win = false;  // later gt wins duplicates
        if (win) {
            float4 gt = gt_boxes[b * GG + t];
            float4 an = anchors[aidx];
            size_t idx = (size_t)b * AA + aidx;
            float4 enc;
            enc.x = (gt.x - an.x) / an.z;
            enc.y = (gt.y - an.y) / an.w;
            enc.z = logf(gt.z) - logf(an.z);
            enc.w = logf(gt.w) - logf(an.w);
            g_tloc[idx] = enc;
            g_tlab[idx] = gt_labels[b * GG + t];
        }
    }
    __syncthreads();  // scatter visible block-wide

    // ---- step 2: load labs, count positives ----
    int lab[KV];
    unsigned v[KV];
    int np = 0;
#pragma unroll
    for (int it = 0; it < KV; it++) {
        int i = t + it * 1024;
        lab[it] = (i < AA) ? g_tlab[(size_t)b * AA + i] : 0;
        bool pos = lab[it] > 0;
        np += pos ? 1 : 0;
        v[it] = pos ? 0u : __float_as_uint(rawv[it]);  // positives excluded
    }
#pragma unroll
    for (int o = 16; o; o >>= 1) np += __shfl_xor_sync(0xffffffffu, np, o);
    if (lane == 0) siA[w] = np;
    __syncthreads();
    if (t < 32) {
        int x = siA[t];
#pragma unroll
        for (int o = 16; o; o >>= 1) x += __shfl_xor_sync(0xffffffffu, x, o);
        if (t == 0) siA[32] = x;
    }
    __syncthreads();
    int np_total = siA[32];
    int k = min(NEG_RATIO * np_total, AA - 1);

    // ---- step 3: positive losses (rare gathers) ----
    float cp = 0.0f, ls = 0.0f;
#pragma unroll
    for (int it = 0; it < KV; it++) {
        if (lab[it] > 0) {
            size_t row = (size_t)b * AA + t + it * 1024;
            float c0   = conf[row * CC];
            float clab = conf[row * CC + lab[it]];
            cp += rawv[it] + c0 - clab;  // = lse - conf[lab]
            float4 lp = locp[row];
            float4 tl = g_tloc[row];
            ls += smooth_l1(lp.x - tl.x) + smooth_l1(lp.y - tl.y) +
                  smooth_l1(lp.z - tl.z) + smooth_l1(lp.w - tl.w);
        }
    }

    // ---- step 4: 3-round radix select ----
    float s = 0.0f;
    int cgt = 0;
    float vk = 0.0f;
    if (k > 0) {
#pragma unroll
        for (int it = 0; it < KV; it++) {
            int bin = (int)(v[it] >> 23);
            unsigned m = __match_any_sync(0xffffffffu, bin);
            if (lane == __ffs(m) - 1) atomicAdd(&h1[bin], __popc(m));
        }
        __syncthreads();
        find_bin_block(h1, 256, 1, k, sres, swarp);
        int E = sres[0];
        int k2 = k - sres[1];

#pragma unroll
        for (int it = 0; it < KV; it++) {
            if ((int)(v[it] >> 23) == E)
                atomicAdd(&h2[(v[it] >> 12) & 2047u], 1);
        }
        __syncthreads();
        find_bin_block(h2, 2048, 2, k2, sres, swarp);
        unsigned P = ((unsigned)E << 11) | (unsigned)sres[0];
        int k3 = k2 - sres[1];

#pragma unroll
        for (int it = 0; it < KV; it++) {
            if ((v[it] >> 12) == P)
                atomicAdd(&h3[v[it] & 4095u], 1);
        }
        __syncthreads();
        find_bin_block(h3, 4096, 4, k3, sres, swarp);
        unsigned lo = (P << 12) | (unsigned)sres[0];  // exact k-th largest bits
        vk = __uint_as_float(lo);

#pragma unroll
        for (int it = 0; it < KV; it++) {
            if (v[it] > lo) { s += __uint_as_float(v[it]); cgt++; }
        }
    }

    // ---- step 5: combined block reduce ----
#pragma unroll
    for (int o = 16; o; o >>= 1) {
        cp  += __shfl_xor_sync(0xffffffffu, cp, o);
        ls  += __shfl_xor_sync(0xffffffffu, ls, o);
        s   += __shfl_xor_sync(0xffffffffu, s, o);
        cgt += __shfl_xor_sync(0xffffffffu, cgt, o);
    }
    if (lane == 0) { sfA[w] = cp; sfB[w] = ls; sfC[w] = s; siB[w] = cgt; }
    __syncthreads();
    if (t == 0) {
        float cpt = 0.f, lst = 0.f, st = 0.f;
        int cgtt = 0;
#pragma unroll
        for (int w2 = 0; w2 < 32; w2++) {
            cpt += sfA[w2]; lst += sfB[w2]; st += sfC[w2]; cgtt += siB[w2];
        }
        float result = (k > 0) ? (st + (float)(k - cgtt) * vk) : 0.0f;
        g_bres[b] = make_float4(lst, cpt, result, (float)np_total);
        __threadfence();
        int done = atomicAdd(&g_done, 1);
        slast = (done == BB - 1) ? 1 : 0;
    }
    __syncthreads();

    // ---- step 6: last block does parallel final combine ----
    if (slast && w < 2) {  // threads 0..63, one per batch
        float4 r = g_bres[t];
        float loc = r.x, cpos = r.y, cn = r.z;
        int npb = (int)r.w;
        int nsb = npb + min(NEG_RATIO * npb, AA - 1);
#pragma unroll
        for (int o = 16; o; o >>= 1) {
            loc  += __shfl_xor_sync(0xffffffffu, loc, o);
            cpos += __shfl_xor_sync(0xffffffffu, cpos, o);
            cn   += __shfl_xor_sync(0xffffffffu, cn, o);
            npb  += __shfl_xor_sync(0xffffffffu, npb, o);
            nsb  += __shfl_xor_sync(0xffffffffu, nsb, o);
        }
        if (lane == 0) {
            sfA[w] = loc; sfB[w] = cpos; sfC[w] = cn;
            siA[w] = npb; siB[w] = nsb;
        }
        __syncwarp();
        if (t == 0) {
            float loct = sfA[0] + sfA[1];
            float cpt  = sfB[0] + sfB[1];
            float cnt  = sfC[0] + sfC[1];
            long long npt = siA[0] + siA[1];
            long long nst = siB[0] + siB[1];
            float cls = cpt + cnt +
                        (float)((long long)BB * AA - nst) * logf((float)CC);
            out[0] = (loct + cls) / (float)npt;
        }
    }
}

// ---------------- launch ----------------
extern "C" void kernel_launch(void* const* d_in, const int* in_sizes, int n_in,
                              void* d_out, int out_size) {
    const float4* loc_pred  = (const float4*)d_in[0];
    const float*  conf_pred = (const float*)d_in[1];
    const float4* anchors   = (const float4*)d_in[2];
    const float4* gt_boxes  = (const float4*)d_in[3];
    const int*    gt_labels = (const int*)d_in[4];
    float* out = (float*)d_out;

    dim3 gf(NB3 + NB1, BB);
    f1_fused<<<gf, 256>>>(conf_pred, anchors, gt_boxes, gt_labels);

    k4_final<<<BB, 1024>>>(conf_pred, loc_pred, anchors, gt_boxes, gt_labels, out);
}